// round 4
// baseline (speedup 1.0000x reference)
#include <cuda_runtime.h>

typedef unsigned long long ull;

#define B_    1024
#define N_    64
#define C_    16
#define M_    16
#define H_    512
#define T_    128
#define DIN_  80
#define ROWS  8
#define NTHR  1024

// ---- packed f32x2 helpers (FFMA2 path: 2 MACs / instruction) ----
__device__ __forceinline__ ull fdup(float v){
    ull r; asm("mov.b64 %0, {%1, %1};" : "=l"(r) : "f"(v)); return r;
}
__device__ __forceinline__ void funpack(ull v, float &a, float &b){
    asm("mov.b64 {%0, %1}, %2;" : "=f"(a), "=f"(b) : "l"(v));
}
#define FFMA2(acc, a, b) asm("fma.rn.f32x2 %0, %1, %2, %0;" : "+l"(acc) : "l"(a), "l"(b))

struct SM {
    float sx [DIN_][ROWS];      // x transposed: [i][row]
    float shm[H_][ROWS];        // h_mu transposed (rows of 32B, 16B-aligned)
    float shs[H_][ROWS];        // h_sg transposed
    float sy [ROWS][N_];        // persistent state y
    float sz [ROWS][M_];        // noise * sqrt(dt) this step
    float sdr[ROWS][N_];        // drift (incl. bias)
    union {
        float pb[16][ROWS][N_]; // phase-B partials [seg][b][col]
        float pc[ROWS][N_][20]; // phase-C partials [b][n][m] (pad 16->20)
    } p;
};
#define SMEM_BYTES (sizeof(SM))

__global__ void __launch_bounds__(NTHR, 1)
nsde_kernel(const float* __restrict__ y0,
            const float* __restrict__ controls,
            const float* __restrict__ noise,
            const float* __restrict__ W1mu, const float* __restrict__ b1mu,
            const float* __restrict__ W2mu, const float* __restrict__ b2mu,
            const float* __restrict__ W1sg, const float* __restrict__ b1sg,
            const float* __restrict__ W2sg, const float* __restrict__ b2sg,
            float* __restrict__ out)
{
    extern __shared__ char smem_raw[];
    SM* s = (SM*)smem_raw;

    const int t  = threadIdx.x;
    const int r0 = blockIdx.x * ROWS;

    // init y, write trajectory slice t=0  (ROWS*N_ = 512)
    if (t < ROWS*N_){
        int b = t >> 6, n = t & 63;
        float v = y0[(r0+b)*N_ + n];
        s->sy[b][n] = v;
        out[(size_t)(r0+b)*N_ + n] = v;
    }
    __syncthreads();

    // phase-A per-thread constants (warp-uniform selects)
    const int  half = t >> 9;          // 0 = mu, 1 = sg
    const int  ja   = t & 511;         // hidden unit
    const float* W1  = half ? W1sg : W1mu;
    const float  b1  = half ? b1sg[ja] : b1mu[ja];
    float (*hdst)[ROWS] = half ? s->shs : s->shm;

    for (int k = 0; k < T_-1; k++){
        // ---- build x (transposed) and pre-scaled noise ----
        if (t < DIN_*ROWS){
            int ii = t >> 3, b = t & 7;
            s->sx[ii][b] = (ii < N_) ? s->sy[b][ii] : controls[k*C_ + (ii - N_)];
        }
        else if (t >= 896 && t < 896 + ROWS*M_){
            int i = t - 896;
            int b = i >> 4, m = i & 15;
            s->sz[b][m] = noise[((size_t)k*B_ + r0 + b)*M_ + m] * 0.1f;
        }
        __syncthreads();

        // ---- Phase A: one hidden unit of one MLP per thread ----
        {
            ull acc[4] = {0ull,0ull,0ull,0ull};
            const float* w = W1 + ja;
            #pragma unroll 5
            for (int i=0;i<DIN_;i++){
                ull wd = fdup(w[(size_t)i*H_]);
                #pragma unroll
                for (int p=0;p<4;p++){
                    ull xv = *(const ull*)&s->sx[i][2*p];
                    FFMA2(acc[p], xv, wd);
                }
            }
            float o[8];
            #pragma unroll
            for (int p=0;p<4;p++) funpack(acc[p], o[2*p], o[2*p+1]);
            #pragma unroll
            for (int q=0;q<8;q++) o[q] = fmaxf(o[q] + b1, 0.f);
            *(float4*)&hdst[ja][0] = make_float4(o[0],o[1],o[2],o[3]);
            *(float4*)&hdst[ja][4] = make_float4(o[4],o[5],o[6],o[7]);
        }
        __syncthreads();

        // ---- Phase B: drift partials (64 cols x 16 K-segments of 32) ----
        {
            const int col = t & 63;
            const int seg = t >> 6;
            ull acc[4] = {0ull,0ull,0ull,0ull};
            const float* w2 = W2mu + (size_t)(seg*32)*N_ + col;
            #pragma unroll 8
            for (int kk=0; kk<32; kk++){
                ull wd = fdup(w2[(size_t)kk*N_]);
                const int ki = seg*32 + kk;
                #pragma unroll
                for (int p=0;p<4;p++){
                    ull hv = *(const ull*)&s->shm[ki][2*p];
                    FFMA2(acc[p], hv, wd);
                }
            }
            #pragma unroll
            for (int p=0;p<4;p++){
                float a, b2v; funpack(acc[p], a, b2v);
                s->p.pb[seg][2*p  ][col] = a;
                s->p.pb[seg][2*p+1][col] = b2v;
            }
        }
        __syncthreads();
        if (t < ROWS*N_){   // reduce drift partials (conflict-free: lanes = cols)
            int n = t & 63, b = t >> 6;
            float sum = b2mu[n];
            #pragma unroll
            for (int g=0; g<16; g++) sum += s->p.pb[g][b][n];
            s->sdr[b][n] = sum;
        }
        __syncthreads();

        // ---- Phase C: diffusion GEMM fused with dW contraction ----
        {
            const int j = t;                    // one diffvec column
            ull acc[4] = {0ull,0ull,0ull,0ull};
            const float* wp = W2sg + j;
            #pragma unroll 8
            for (int kk=0; kk<H_; kk++){
                ull wd = fdup(wp[(size_t)kk*1024]);
                ulonglong2 u0 = *(const ulonglong2*)&s->shs[kk][0];
                ulonglong2 u1 = *(const ulonglong2*)&s->shs[kk][4];
                FFMA2(acc[0], u0.x, wd);
                FFMA2(acc[1], u0.y, wd);
                FFMA2(acc[2], u1.x, wd);
                FFMA2(acc[3], u1.y, wd);
            }
            const int n = j >> 4;
            const int m = j & 15;
            float bias = b2sg[j];
            float o[8];
            #pragma unroll
            for (int p=0;p<4;p++) funpack(acc[p], o[2*p], o[2*p+1]);
            #pragma unroll
            for (int b=0;b<8;b++)
                s->p.pc[b][n][m] = (o[b] + bias) * s->sz[b][m];
        }
        __syncthreads();

        // ---- y update + trajectory write ----
        if (t < ROWS*N_){
            int n = t & 63, b = t >> 6;
            float yn = s->sy[b][n] + 0.01f * s->sdr[b][n];
            const float4* q = (const float4*)&s->p.pc[b][n][0];
            float4 c0 = q[0], c1 = q[1], c2 = q[2], c3 = q[3];
            yn += (c0.x+c0.y+c0.z+c0.w) + (c1.x+c1.y+c1.z+c1.w)
                + (c2.x+c2.y+c2.z+c2.w) + (c3.x+c3.y+c3.z+c3.w);
            s->sy[b][n] = yn;
            out[((size_t)(k+1)*B_ + r0 + b)*N_ + n] = yn;
        }
        __syncthreads();
    }
}

extern "C" void kernel_launch(void* const* d_in, const int* in_sizes, int n_in,
                              void* d_out, int out_size)
{
    (void)in_sizes; (void)n_in; (void)out_size;
    cudaFuncSetAttribute(nsde_kernel,
                         cudaFuncAttributeMaxDynamicSharedMemorySize,
                         (int)SMEM_BYTES);
    nsde_kernel<<<B_/ROWS, NTHR, SMEM_BYTES>>>(
        (const float*)d_in[0],  // y0
        (const float*)d_in[1],  // controls
        (const float*)d_in[2],  // noise
        (const float*)d_in[3],  // W1_mu
        (const float*)d_in[4],  // b1_mu
        (const float*)d_in[5],  // W2_mu
        (const float*)d_in[6],  // b2_mu
        (const float*)d_in[7],  // W1_sg
        (const float*)d_in[8],  // b1_sg
        (const float*)d_in[9],  // W2_sg
        (const float*)d_in[10], // b2_sg
        (float*)d_out);
}

// round 6
// speedup vs baseline: 1.1287x; 1.1287x over previous
#include <cuda_runtime.h>

typedef unsigned long long ull;

#define B_    1024
#define N_    64
#define C_    16
#define M_    16
#define H_    512
#define T_    128
#define DIN_  80
#define ROWS  8
#define NTHR  512

// ---- packed f32x2 helpers (FFMA2 path: 2 MACs / instruction) ----
__device__ __forceinline__ ull fdup(float v){
    ull r; asm("mov.b64 %0, {%1, %1};" : "=l"(r) : "f"(v)); return r;
}
__device__ __forceinline__ void funpack(ull v, float &a, float &b){
    asm("mov.b64 {%0, %1}, %2;" : "=f"(a), "=f"(b) : "l"(v));
}
#define FFMA2(acc, a, b) asm("fma.rn.f32x2 %0, %1, %2, %0;" : "+l"(acc) : "l"(a), "l"(b))

__global__ void __launch_bounds__(NTHR, 1)
nsde_kernel(const float* __restrict__ y0,
            const float* __restrict__ controls,
            const float* __restrict__ noise,
            const float* __restrict__ W1mu, const float* __restrict__ b1mu,
            const float* __restrict__ W2mu, const float* __restrict__ b2mu,
            const float* __restrict__ W1sg, const float* __restrict__ b1sg,
            const float* __restrict__ W2sg, const float* __restrict__ b2sg,
            float* __restrict__ out)
{
    __shared__ float sx [DIN_][ROWS];   // x transposed: [i][row], 32B rows
    __shared__ float shm[H_][ROWS];     // h_mu transposed
    __shared__ float shs[H_][ROWS];     // h_sg transposed
    __shared__ float sy [ROWS][N_];     // persistent state y
    __shared__ float sz [ROWS][M_];     // noise * sqrt(dt) this step
    __shared__ float sdp[8][N_][ROWS];  // partials (phase B, reused phase C)
    __shared__ float sdr[ROWS][N_];     // drift (incl. bias)

    const int t  = threadIdx.x;
    const int r0 = blockIdx.x * ROWS;

    // init y, write trajectory slice t=0  (ROWS*N_ = 512 = NTHR)
    {
        int b = t >> 6, n = t & 63;
        float v = y0[(r0+b)*N_ + n];
        sy[b][n] = v;
        out[(size_t)(r0+b)*N_ + n] = v;
    }
    __syncthreads();

    for (int k = 0; k < T_-1; k++){
        // ---- build x (transposed) and pre-scaled noise ----
        for (int i = t; i < DIN_*ROWS; i += NTHR){
            int ii = i >> 3, b = i & 7;
            sx[ii][b] = (ii < N_) ? sy[b][ii] : controls[k*C_ + (ii - N_)];
        }
        if (t < ROWS*M_){
            int b = t >> 4, m = t & 15;
            sz[b][m] = noise[((size_t)k*B_ + r0 + b)*M_ + m] * 0.1f;
        }
        __syncthreads();

        // ---- Phase A: h_mu[j], h_sg[j] for j = t (one unit each) ----
        {
            const int j = t;
            ull am[4], as2[4];
            #pragma unroll
            for (int p=0;p<4;p++){ am[p]=0ull; as2[p]=0ull; }
            const float* wm = W1mu + j;
            const float* ws = W1sg + j;
            #pragma unroll 5
            for (int i=0;i<DIN_;i++){
                ull wmd = fdup(wm[(size_t)i*H_]);
                ull wsd = fdup(ws[(size_t)i*H_]);
                ulonglong2 x0 = *(const ulonglong2*)&sx[i][0];
                ulonglong2 x1 = *(const ulonglong2*)&sx[i][4];
                FFMA2(am [0], x0.x, wmd); FFMA2(am [1], x0.y, wmd);
                FFMA2(am [2], x1.x, wmd); FFMA2(am [3], x1.y, wmd);
                FFMA2(as2[0], x0.x, wsd); FFMA2(as2[1], x0.y, wsd);
                FFMA2(as2[2], x1.x, wsd); FFMA2(as2[3], x1.y, wsd);
            }
            float bm = b1mu[j], bs = b1sg[j];
            float o[8];
            #pragma unroll
            for (int p=0;p<4;p++) funpack(am[p], o[2*p], o[2*p+1]);
            #pragma unroll
            for (int q=0;q<8;q++) o[q] = fmaxf(o[q] + bm, 0.f);
            *(float4*)&shm[j][0] = make_float4(o[0],o[1],o[2],o[3]);
            *(float4*)&shm[j][4] = make_float4(o[4],o[5],o[6],o[7]);
            #pragma unroll
            for (int p=0;p<4;p++) funpack(as2[p], o[2*p], o[2*p+1]);
            #pragma unroll
            for (int q=0;q<8;q++) o[q] = fmaxf(o[q] + bs, 0.f);
            *(float4*)&shs[j][0] = make_float4(o[0],o[1],o[2],o[3]);
            *(float4*)&shs[j][4] = make_float4(o[4],o[5],o[6],o[7]);
        }
        __syncthreads();

        // ---- Phase B: drift partials (64 cols x 8 K-segments of 64) ----
        {
            const int col = t & 63;
            const int seg = t >> 6;
            ull acc[4] = {0ull,0ull,0ull,0ull};
            const float* w2 = W2mu + (size_t)(seg*64)*N_ + col;
            #pragma unroll 8
            for (int kk=0; kk<64; kk++){
                ull wd = fdup(w2[(size_t)kk*N_]);
                const int ki = seg*64 + kk;
                ulonglong2 h0 = *(const ulonglong2*)&shm[ki][0];
                ulonglong2 h1 = *(const ulonglong2*)&shm[ki][4];
                FFMA2(acc[0], h0.x, wd); FFMA2(acc[1], h0.y, wd);
                FFMA2(acc[2], h1.x, wd); FFMA2(acc[3], h1.y, wd);
            }
            #pragma unroll
            for (int p=0;p<4;p++){
                float a, b2v; funpack(acc[p], a, b2v);
                sdp[seg][col][2*p]   = a;
                sdp[seg][col][2*p+1] = b2v;
            }
        }
        __syncthreads();
        {   // reduce drift partials (512 threads = 8 rows x 64 cols)
            int n = t & 63, b = t >> 6;
            float s = b2mu[n];
            #pragma unroll
            for (int g=0; g<8; g++) s += sdp[g][n][b];
            sdr[b][n] = s;
        }
        __syncthreads();

        // ---- Phase C: diffusion GEMM fused with dW contraction ----
        {
            const int j0 = 2*t;                 // 2 consecutive diffvec columns
            ull acc[2][4];
            #pragma unroll
            for (int c=0;c<2;c++)
                #pragma unroll
                for(int p=0;p<4;p++) acc[c][p]=0ull;
            const float2* wp = (const float2*)(W2sg + j0);
            #pragma unroll 4
            for (int kk=0; kk<H_; kk++){
                float2 w = wp[(size_t)kk*(1024/2)];
                ull wd0=fdup(w.x), wd1=fdup(w.y);
                ulonglong2 u0 = *(const ulonglong2*)&shs[kk][0];
                ulonglong2 u1 = *(const ulonglong2*)&shs[kk][4];
                FFMA2(acc[0][0],u0.x,wd0); FFMA2(acc[0][1],u0.y,wd0);
                FFMA2(acc[0][2],u1.x,wd0); FFMA2(acc[0][3],u1.y,wd0);
                FFMA2(acc[1][0],u0.x,wd1); FFMA2(acc[1][1],u0.y,wd1);
                FFMA2(acc[1][2],u1.x,wd1); FFMA2(acc[1][3],u1.y,wd1);
            }
            // epilogue: columns j0,j0+1 -> (n = t>>3, m = 2g, 2g+1), g = t&7
            const int n  = t >> 3;
            const int g  = t & 7;
            float bias0 = b2sg[j0], bias1 = b2sg[j0+1];
            float cont[ROWS];
            #pragma unroll
            for (int p=0;p<4;p++){
                float a0, b0, a1, b1v;
                funpack(acc[0][p], a0, b0);
                funpack(acc[1][p], a1, b1v);
                cont[2*p]   = (a0  + bias0) * sz[2*p  ][2*g]
                            + (a1  + bias1) * sz[2*p  ][2*g+1];
                cont[2*p+1] = (b0  + bias0) * sz[2*p+1][2*g]
                            + (b1v + bias1) * sz[2*p+1][2*g+1];
            }
            #pragma unroll
            for (int b=0;b<ROWS;b++) sdp[g][n][b] = cont[b];
        }
        __syncthreads();

        // ---- y update + trajectory write (512 threads = 8 rows x 64 cols) ----
        {
            int n = t & 63, b = t >> 6;
            float yn = sy[b][n] + 0.01f * sdr[b][n];
            #pragma unroll
            for (int g=0; g<8; g++) yn += sdp[g][n][b];
            sy[b][n] = yn;
            out[((size_t)(k+1)*B_ + r0 + b)*N_ + n] = yn;
        }
        __syncthreads();
    }
}

extern "C" void kernel_launch(void* const* d_in, const int* in_sizes, int n_in,
                              void* d_out, int out_size)
{
    (void)in_sizes; (void)n_in; (void)out_size;
    nsde_kernel<<<B_/ROWS, NTHR>>>(
        (const float*)d_in[0],  // y0
        (const float*)d_in[1],  // controls
        (const float*)d_in[2],  // noise
        (const float*)d_in[3],  // W1_mu
        (const float*)d_in[4],  // b1_mu
        (const float*)d_in[5],  // W2_mu
        (const float*)d_in[6],  // b2_mu
        (const float*)d_in[7],  // W1_sg
        (const float*)d_in[8],  // b1_sg
        (const float*)d_in[9],  // W2_sg
        (const float*)d_in[10], // b2_sg
        (float*)d_out);
}

// round 7
// speedup vs baseline: 1.4878x; 1.3182x over previous
#include <cuda_runtime.h>

typedef unsigned long long ull;

#define B_    1024
#define N_    64
#define C_    16
#define M_    16
#define H_    512
#define T_    128
#define DIN_  80
#define ROWS  8
#define NTHR  512

// ---- packed f32x2 helpers (FFMA2 path: 2 MACs / instruction) ----
__device__ __forceinline__ ull fdup(float v){
    ull r; asm("mov.b64 %0, {%1, %1};" : "=l"(r) : "f"(v)); return r;
}
__device__ __forceinline__ void funpack(ull v, float &a, float &b){
    asm("mov.b64 {%0, %1}, %2;" : "=f"(a), "=f"(b) : "l"(v));
}
#define FFMA2(acc, a, b) asm("fma.rn.f32x2 %0, %1, %2, %0;" : "+l"(acc) : "l"(a), "l"(b))

__global__ void __launch_bounds__(NTHR, 1)
nsde_kernel(const float* __restrict__ y0,
            const float* __restrict__ controls,
            const float* __restrict__ noise,
            const float* __restrict__ W1mu, const float* __restrict__ b1mu,
            const float* __restrict__ W2mu, const float* __restrict__ b2mu,
            const float* __restrict__ W1sg, const float* __restrict__ b1sg,
            const float* __restrict__ W2sg, const float* __restrict__ b2sg,
            float* __restrict__ out)
{
    __shared__ float sx [DIN_][ROWS];   // x transposed: [i][row], 32B rows
    __shared__ float shm[H_][ROWS];     // h_mu transposed
    __shared__ float shs[H_][ROWS];     // h_sg transposed
    __shared__ float sy [ROWS][N_];     // persistent state y
    __shared__ float sz [ROWS][M_];     // noise * sqrt(dt) this step
    __shared__ float sdp[8][N_][ROWS];  // partials (phase B, reused phase C)
    __shared__ float sdr[ROWS][N_];     // drift (incl. bias)

    const int t  = threadIdx.x;
    const int r0 = blockIdx.x * ROWS;

    // init y, write trajectory slice t=0  (ROWS*N_ = 512 = NTHR)
    {
        int b = t >> 6, n = t & 63;
        float v = y0[(r0+b)*N_ + n];
        sy[b][n] = v;
        out[(size_t)(r0+b)*N_ + n] = v;
    }
    __syncthreads();

    for (int k = 0; k < T_-1; k++){
        // ---- build x (transposed) and pre-scaled noise ----
        for (int i = t; i < DIN_*ROWS; i += NTHR){
            int ii = i >> 3, b = i & 7;
            sx[ii][b] = (ii < N_) ? sy[b][ii] : controls[k*C_ + (ii - N_)];
        }
        if (t < ROWS*M_){
            int b = t >> 4, m = t & 15;
            sz[b][m] = noise[((size_t)k*B_ + r0 + b)*M_ + m] * 0.1f;
        }
        __syncthreads();

        // ---- Phase A: h_mu[j], h_sg[j] for j = t; 8-deep dbl-buffered LDG ----
        {
            const int j = t;
            const float* wm = W1mu + j;
            const float* ws = W1sg + j;
            float wm0[8], ws0[8], wm1[8], ws1[8];
            #pragma unroll
            for (int q=0;q<8;q++){
                wm0[q] = wm[(size_t)q*H_];
                ws0[q] = ws[(size_t)q*H_];
            }
            ull am[4], as2[4];
            #pragma unroll
            for (int p=0;p<4;p++){ am[p]=0ull; as2[p]=0ull; }

            #pragma unroll 1
            for (int b2=0; b2<5; b2++){       // 10 blocks of 8, processed in pairs
                const int base = b2*16;
                #pragma unroll
                for (int q=0;q<8;q++){
                    wm1[q] = wm[(size_t)(base+8+q)*H_];
                    ws1[q] = ws[(size_t)(base+8+q)*H_];
                }
                #pragma unroll
                for (int q=0;q<8;q++){
                    const int i = base + q;
                    ull wmd = fdup(wm0[q]), wsd = fdup(ws0[q]);
                    ulonglong2 x0 = *(const ulonglong2*)&sx[i][0];
                    ulonglong2 x1 = *(const ulonglong2*)&sx[i][4];
                    FFMA2(am [0], x0.x, wmd); FFMA2(am [1], x0.y, wmd);
                    FFMA2(am [2], x1.x, wmd); FFMA2(am [3], x1.y, wmd);
                    FFMA2(as2[0], x0.x, wsd); FFMA2(as2[1], x0.y, wsd);
                    FFMA2(as2[2], x1.x, wsd); FFMA2(as2[3], x1.y, wsd);
                }
                if (b2 < 4){
                    #pragma unroll
                    for (int q=0;q<8;q++){
                        wm0[q] = wm[(size_t)(base+16+q)*H_];
                        ws0[q] = ws[(size_t)(base+16+q)*H_];
                    }
                }
                #pragma unroll
                for (int q=0;q<8;q++){
                    const int i = base + 8 + q;
                    ull wmd = fdup(wm1[q]), wsd = fdup(ws1[q]);
                    ulonglong2 x0 = *(const ulonglong2*)&sx[i][0];
                    ulonglong2 x1 = *(const ulonglong2*)&sx[i][4];
                    FFMA2(am [0], x0.x, wmd); FFMA2(am [1], x0.y, wmd);
                    FFMA2(am [2], x1.x, wmd); FFMA2(am [3], x1.y, wmd);
                    FFMA2(as2[0], x0.x, wsd); FFMA2(as2[1], x0.y, wsd);
                    FFMA2(as2[2], x1.x, wsd); FFMA2(as2[3], x1.y, wsd);
                }
            }

            float bm = b1mu[j], bs = b1sg[j];
            float o[8];
            #pragma unroll
            for (int p=0;p<4;p++) funpack(am[p], o[2*p], o[2*p+1]);
            #pragma unroll
            for (int q=0;q<8;q++) o[q] = fmaxf(o[q] + bm, 0.f);
            *(float4*)&shm[j][0] = make_float4(o[0],o[1],o[2],o[3]);
            *(float4*)&shm[j][4] = make_float4(o[4],o[5],o[6],o[7]);
            #pragma unroll
            for (int p=0;p<4;p++) funpack(as2[p], o[2*p], o[2*p+1]);
            #pragma unroll
            for (int q=0;q<8;q++) o[q] = fmaxf(o[q] + bs, 0.f);
            *(float4*)&shs[j][0] = make_float4(o[0],o[1],o[2],o[3]);
            *(float4*)&shs[j][4] = make_float4(o[4],o[5],o[6],o[7]);
        }
        __syncthreads();

        // ---- Phase B: drift partials; 8-deep dbl-buffered LDG ----
        {
            const int col = t & 63;
            const int seg = t >> 6;
            const float* w2 = W2mu + (size_t)(seg*64)*N_ + col;
            float wv0[8], wv1[8];
            #pragma unroll
            for (int q=0;q<8;q++) wv0[q] = w2[(size_t)q*N_];
            ull acc[4] = {0ull,0ull,0ull,0ull};

            #pragma unroll 1
            for (int b2=0; b2<4; b2++){       // 8 blocks of 8, in pairs
                const int base = b2*16;
                #pragma unroll
                for (int q=0;q<8;q++) wv1[q] = w2[(size_t)(base+8+q)*N_];
                #pragma unroll
                for (int q=0;q<8;q++){
                    const int ki = seg*64 + base + q;
                    ull wd = fdup(wv0[q]);
                    ulonglong2 h0 = *(const ulonglong2*)&shm[ki][0];
                    ulonglong2 h1 = *(const ulonglong2*)&shm[ki][4];
                    FFMA2(acc[0], h0.x, wd); FFMA2(acc[1], h0.y, wd);
                    FFMA2(acc[2], h1.x, wd); FFMA2(acc[3], h1.y, wd);
                }
                if (b2 < 3){
                    #pragma unroll
                    for (int q=0;q<8;q++) wv0[q] = w2[(size_t)(base+16+q)*N_];
                }
                #pragma unroll
                for (int q=0;q<8;q++){
                    const int ki = seg*64 + base + 8 + q;
                    ull wd = fdup(wv1[q]);
                    ulonglong2 h0 = *(const ulonglong2*)&shm[ki][0];
                    ulonglong2 h1 = *(const ulonglong2*)&shm[ki][4];
                    FFMA2(acc[0], h0.x, wd); FFMA2(acc[1], h0.y, wd);
                    FFMA2(acc[2], h1.x, wd); FFMA2(acc[3], h1.y, wd);
                }
            }
            #pragma unroll
            for (int p=0;p<4;p++){
                float a, b2v; funpack(acc[p], a, b2v);
                sdp[seg][col][2*p]   = a;
                sdp[seg][col][2*p+1] = b2v;
            }
        }
        __syncthreads();
        {   // reduce drift partials (512 threads = 8 rows x 64 cols)
            int n = t & 63, b = t >> 6;
            float s = b2mu[n];
            #pragma unroll
            for (int g=0; g<8; g++) s += sdp[g][n][b];
            sdr[b][n] = s;
        }
        __syncthreads();

        // ---- Phase C: diffusion GEMM + dW contraction; 8-deep dbl-buffered ----
        {
            const int j0 = 2*t;
            const char* pw = (const char*)(W2sg + j0);   // row stride 4096B
            float2 w0[8], w1[8];
            #pragma unroll
            for (int q=0;q<8;q++)
                w0[q] = *(const float2*)(pw + (size_t)q*4096);
            ull acc[2][4];
            #pragma unroll
            for (int c=0;c<2;c++)
                #pragma unroll
                for(int p=0;p<4;p++) acc[c][p]=0ull;

            #pragma unroll 1
            for (int b2=0; b2<32; b2++){      // 64 blocks of 8, in pairs
                const int base = b2*16;
                #pragma unroll
                for (int q=0;q<8;q++)
                    w1[q] = *(const float2*)(pw + (size_t)(base+8+q)*4096);
                #pragma unroll
                for (int q=0;q<8;q++){
                    const int kk = base + q;
                    ull wd0=fdup(w0[q].x), wd1=fdup(w0[q].y);
                    ulonglong2 u0 = *(const ulonglong2*)&shs[kk][0];
                    ulonglong2 u1 = *(const ulonglong2*)&shs[kk][4];
                    FFMA2(acc[0][0],u0.x,wd0); FFMA2(acc[0][1],u0.y,wd0);
                    FFMA2(acc[0][2],u1.x,wd0); FFMA2(acc[0][3],u1.y,wd0);
                    FFMA2(acc[1][0],u0.x,wd1); FFMA2(acc[1][1],u0.y,wd1);
                    FFMA2(acc[1][2],u1.x,wd1); FFMA2(acc[1][3],u1.y,wd1);
                }
                if (b2 < 31){
                    #pragma unroll
                    for (int q=0;q<8;q++)
                        w0[q] = *(const float2*)(pw + (size_t)(base+16+q)*4096);
                }
                #pragma unroll
                for (int q=0;q<8;q++){
                    const int kk = base + 8 + q;
                    ull wd0=fdup(w1[q].x), wd1=fdup(w1[q].y);
                    ulonglong2 u0 = *(const ulonglong2*)&shs[kk][0];
                    ulonglong2 u1 = *(const ulonglong2*)&shs[kk][4];
                    FFMA2(acc[0][0],u0.x,wd0); FFMA2(acc[0][1],u0.y,wd0);
                    FFMA2(acc[0][2],u1.x,wd0); FFMA2(acc[0][3],u1.y,wd0);
                    FFMA2(acc[1][0],u0.x,wd1); FFMA2(acc[1][1],u0.y,wd1);
                    FFMA2(acc[1][2],u1.x,wd1); FFMA2(acc[1][3],u1.y,wd1);
                }
            }

            // epilogue: columns j0,j0+1 -> (n = t>>3, m = 2g, 2g+1), g = t&7
            const int n  = t >> 3;
            const int g  = t & 7;
            float bias0 = b2sg[j0], bias1 = b2sg[j0+1];
            float cont[ROWS];
            #pragma unroll
            for (int p=0;p<4;p++){
                float a0, b0, a1, b1v;
                funpack(acc[0][p], a0, b0);
                funpack(acc[1][p], a1, b1v);
                cont[2*p]   = (a0  + bias0) * sz[2*p  ][2*g]
                            + (a1  + bias1) * sz[2*p  ][2*g+1];
                cont[2*p+1] = (b0  + bias0) * sz[2*p+1][2*g]
                            + (b1v + bias1) * sz[2*p+1][2*g+1];
            }
            #pragma unroll
            for (int b=0;b<ROWS;b++) sdp[g][n][b] = cont[b];
        }
        __syncthreads();

        // ---- y update + trajectory write (512 threads = 8 rows x 64 cols) ----
        {
            int n = t & 63, b = t >> 6;
            float yn = sy[b][n] + 0.01f * sdr[b][n];
            #pragma unroll
            for (int g=0; g<8; g++) yn += sdp[g][n][b];
            sy[b][n] = yn;
            out[((size_t)(k+1)*B_ + r0 + b)*N_ + n] = yn;
        }
        __syncthreads();
    }
}

extern "C" void kernel_launch(void* const* d_in, const int* in_sizes, int n_in,
                              void* d_out, int out_size)
{
    (void)in_sizes; (void)n_in; (void)out_size;
    nsde_kernel<<<B_/ROWS, NTHR>>>(
        (const float*)d_in[0],  // y0
        (const float*)d_in[1],  // controls
        (const float*)d_in[2],  // noise
        (const float*)d_in[3],  // W1_mu
        (const float*)d_in[4],  // b1_mu
        (const float*)d_in[5],  // W2_mu
        (const float*)d_in[6],  // b2_mu
        (const float*)d_in[7],  // W1_sg
        (const float*)d_in[8],  // b1_sg
        (const float*)d_in[9],  // W2_sg
        (const float*)d_in[10], // b2_sg
        (float*)d_out);
}

// round 8
// speedup vs baseline: 1.5090x; 1.0143x over previous
#include <cuda_runtime.h>

typedef unsigned long long ull;

#define B_    1024
#define N_    64
#define C_    16
#define M_    16
#define H_    512
#define T_    128
#define DIN_  80
#define ROWS  8
#define NTHR  512

// ---- packed f32x2 helpers (FFMA2 path: 2 MACs / instruction) ----
__device__ __forceinline__ ull fdup(float v){
    ull r; asm("mov.b64 %0, {%1, %1};" : "=l"(r) : "f"(v)); return r;
}
__device__ __forceinline__ void funpack(ull v, float &a, float &b){
    asm("mov.b64 {%0, %1}, %2;" : "=f"(a), "=f"(b) : "l"(v));
}
#define FFMA2(acc, a, b) asm("fma.rn.f32x2 %0, %1, %2, %0;" : "+l"(acc) : "l"(a), "l"(b))

__global__ void __launch_bounds__(NTHR, 1)
nsde_kernel(const float* __restrict__ y0,
            const float* __restrict__ controls,
            const float* __restrict__ noise,
            const float* __restrict__ W1mu, const float* __restrict__ b1mu,
            const float* __restrict__ W2mu, const float* __restrict__ b2mu,
            const float* __restrict__ W1sg, const float* __restrict__ b1sg,
            const float* __restrict__ W2sg, const float* __restrict__ b2sg,
            float* __restrict__ out)
{
    __shared__ float sx [DIN_][ROWS];     // x transposed: [i][row], 32B rows
    __shared__ float shm[H_+1][ROWS];     // h_mu transposed (+1 dummy row for lookahead)
    __shared__ float shs[H_+1][ROWS];     // h_sg transposed (+1 dummy row)
    __shared__ float sy [ROWS][N_];       // persistent state y
    __shared__ float sz [ROWS][M_];       // noise * sqrt(dt) this step
    __shared__ float sdp[8][N_][ROWS];    // partials (phase B, reused phase C)
    __shared__ float sdr[ROWS][N_];       // drift (incl. bias)

    const int t  = threadIdx.x;
    const int r0 = blockIdx.x * ROWS;

    // init y, write trajectory slice t=0; zero dummy lookahead rows
    {
        int b = t >> 6, n = t & 63;
        float v = y0[(r0+b)*N_ + n];
        sy[b][n] = v;
        out[(size_t)(r0+b)*N_ + n] = v;
        if (t < ROWS){ shm[H_][t] = 0.f; shs[H_][t] = 0.f; }
    }
    __syncthreads();

    for (int k = 0; k < T_-1; k++){
        // ---- build x (transposed) and pre-scaled noise ----
        for (int i = t; i < DIN_*ROWS; i += NTHR){
            int ii = i >> 3, b = i & 7;
            sx[ii][b] = (ii < N_) ? sy[b][ii] : controls[k*C_ + (ii - N_)];
        }
        if (t < ROWS*M_){
            int b = t >> 4, m = t & 15;
            sz[b][m] = noise[((size_t)k*B_ + r0 + b)*M_ + m] * 0.1f;
        }
        __syncthreads();

        // ---- Phase A: h_mu[j], h_sg[j] for j = t; 8-deep dbl-buffered LDG ----
        {
            const int j = t;
            const float* wm = W1mu + j;
            const float* ws = W1sg + j;
            float wm0[8], ws0[8], wm1[8], ws1[8];
            #pragma unroll
            for (int q=0;q<8;q++){
                wm0[q] = wm[(size_t)q*H_];
                ws0[q] = ws[(size_t)q*H_];
            }
            ull am[4], as2[4];
            #pragma unroll
            for (int p=0;p<4;p++){ am[p]=0ull; as2[p]=0ull; }

            #pragma unroll 1
            for (int b2=0; b2<5; b2++){       // 10 blocks of 8, processed in pairs
                const int base = b2*16;
                #pragma unroll
                for (int q=0;q<8;q++){
                    wm1[q] = wm[(size_t)(base+8+q)*H_];
                    ws1[q] = ws[(size_t)(base+8+q)*H_];
                }
                #pragma unroll
                for (int q=0;q<8;q++){
                    const int i = base + q;
                    ull wmd = fdup(wm0[q]), wsd = fdup(ws0[q]);
                    ulonglong2 x0 = *(const ulonglong2*)&sx[i][0];
                    ulonglong2 x1 = *(const ulonglong2*)&sx[i][4];
                    FFMA2(am [0], x0.x, wmd); FFMA2(am [1], x0.y, wmd);
                    FFMA2(am [2], x1.x, wmd); FFMA2(am [3], x1.y, wmd);
                    FFMA2(as2[0], x0.x, wsd); FFMA2(as2[1], x0.y, wsd);
                    FFMA2(as2[2], x1.x, wsd); FFMA2(as2[3], x1.y, wsd);
                }
                if (b2 < 4){
                    #pragma unroll
                    for (int q=0;q<8;q++){
                        wm0[q] = wm[(size_t)(base+16+q)*H_];
                        ws0[q] = ws[(size_t)(base+16+q)*H_];
                    }
                }
                #pragma unroll
                for (int q=0;q<8;q++){
                    const int i = base + 8 + q;
                    ull wmd = fdup(wm1[q]), wsd = fdup(ws1[q]);
                    ulonglong2 x0 = *(const ulonglong2*)&sx[i][0];
                    ulonglong2 x1 = *(const ulonglong2*)&sx[i][4];
                    FFMA2(am [0], x0.x, wmd); FFMA2(am [1], x0.y, wmd);
                    FFMA2(am [2], x1.x, wmd); FFMA2(am [3], x1.y, wmd);
                    FFMA2(as2[0], x0.x, wsd); FFMA2(as2[1], x0.y, wsd);
                    FFMA2(as2[2], x1.x, wsd); FFMA2(as2[3], x1.y, wsd);
                }
            }

            float bm = b1mu[j], bs = b1sg[j];
            float o[8];
            #pragma unroll
            for (int p=0;p<4;p++) funpack(am[p], o[2*p], o[2*p+1]);
            #pragma unroll
            for (int q=0;q<8;q++) o[q] = fmaxf(o[q] + bm, 0.f);
            *(float4*)&shm[j][0] = make_float4(o[0],o[1],o[2],o[3]);
            *(float4*)&shm[j][4] = make_float4(o[4],o[5],o[6],o[7]);
            #pragma unroll
            for (int p=0;p<4;p++) funpack(as2[p], o[2*p], o[2*p+1]);
            #pragma unroll
            for (int q=0;q<8;q++) o[q] = fmaxf(o[q] + bs, 0.f);
            *(float4*)&shs[j][0] = make_float4(o[0],o[1],o[2],o[3]);
            *(float4*)&shs[j][4] = make_float4(o[4],o[5],o[6],o[7]);
        }
        __syncthreads();

        // ---- Phase B: drift partials; dbl-buffered LDG + pipelined LDS ----
        {
            const int col = t & 63;
            const int seg = t >> 6;
            const float* w2 = W2mu + (size_t)(seg*64)*N_ + col;
            float wv0[8], wv1[8];
            #pragma unroll
            for (int q=0;q<8;q++) wv0[q] = w2[(size_t)q*N_];
            ull acc[4] = {0ull,0ull,0ull,0ull};

            const int k0 = seg*64;
            ulonglong2 u0 = *(const ulonglong2*)&shm[k0][0];
            ulonglong2 u1 = *(const ulonglong2*)&shm[k0][4];

            #pragma unroll 1
            for (int b2=0; b2<4; b2++){       // 8 blocks of 8, in pairs
                const int base = b2*16;
                #pragma unroll
                for (int q=0;q<8;q++) wv1[q] = w2[(size_t)(base+8+q)*N_];
                #pragma unroll
                for (int q=0;q<8;q++){
                    const int ki = k0 + base + q;
                    ulonglong2 n0 = *(const ulonglong2*)&shm[ki+1][0];
                    ulonglong2 n1 = *(const ulonglong2*)&shm[ki+1][4];
                    ull wd = fdup(wv0[q]);
                    FFMA2(acc[0], u0.x, wd); FFMA2(acc[1], u0.y, wd);
                    FFMA2(acc[2], u1.x, wd); FFMA2(acc[3], u1.y, wd);
                    u0 = n0; u1 = n1;
                }
                if (b2 < 3){
                    #pragma unroll
                    for (int q=0;q<8;q++) wv0[q] = w2[(size_t)(base+16+q)*N_];
                }
                #pragma unroll
                for (int q=0;q<8;q++){
                    const int ki = k0 + base + 8 + q;
                    ulonglong2 n0 = *(const ulonglong2*)&shm[ki+1][0];
                    ulonglong2 n1 = *(const ulonglong2*)&shm[ki+1][4];
                    ull wd = fdup(wv1[q]);
                    FFMA2(acc[0], u0.x, wd); FFMA2(acc[1], u0.y, wd);
                    FFMA2(acc[2], u1.x, wd); FFMA2(acc[3], u1.y, wd);
                    u0 = n0; u1 = n1;
                }
            }
            #pragma unroll
            for (int p=0;p<4;p++){
                float a, b2v; funpack(acc[p], a, b2v);
                sdp[seg][col][2*p]   = a;
                sdp[seg][col][2*p+1] = b2v;
            }
        }
        __syncthreads();
        {   // reduce drift partials (512 threads = 8 rows x 64 cols)
            int n = t & 63, b = t >> 6;
            float s = b2mu[n];
            #pragma unroll
            for (int g=0; g<8; g++) s += sdp[g][n][b];
            sdr[b][n] = s;
        }
        __syncthreads();

        // ---- Phase C: diffusion GEMM + dW; dbl-buffered LDG + pipelined LDS ----
        {
            const int j0 = 2*t;
            const char* pw = (const char*)(W2sg + j0);   // row stride 4096B
            float2 w0[8], w1[8];
            #pragma unroll
            for (int q=0;q<8;q++)
                w0[q] = *(const float2*)(pw + (size_t)q*4096);
            ull acc[2][4];
            #pragma unroll
            for (int c=0;c<2;c++)
                #pragma unroll
                for(int p=0;p<4;p++) acc[c][p]=0ull;

            ulonglong2 u0 = *(const ulonglong2*)&shs[0][0];
            ulonglong2 u1 = *(const ulonglong2*)&shs[0][4];

            #pragma unroll 1
            for (int b2=0; b2<32; b2++){      // 64 blocks of 8, in pairs
                const int base = b2*16;
                #pragma unroll
                for (int q=0;q<8;q++)
                    w1[q] = *(const float2*)(pw + (size_t)(base+8+q)*4096);
                #pragma unroll
                for (int q=0;q<8;q++){
                    const int kk = base + q;
                    ulonglong2 n0 = *(const ulonglong2*)&shs[kk+1][0];
                    ulonglong2 n1 = *(const ulonglong2*)&shs[kk+1][4];
                    ull wd0=fdup(w0[q].x), wd1=fdup(w0[q].y);
                    FFMA2(acc[0][0],u0.x,wd0); FFMA2(acc[0][1],u0.y,wd0);
                    FFMA2(acc[0][2],u1.x,wd0); FFMA2(acc[0][3],u1.y,wd0);
                    FFMA2(acc[1][0],u0.x,wd1); FFMA2(acc[1][1],u0.y,wd1);
                    FFMA2(acc[1][2],u1.x,wd1); FFMA2(acc[1][3],u1.y,wd1);
                    u0 = n0; u1 = n1;
                }
                if (b2 < 31){
                    #pragma unroll
                    for (int q=0;q<8;q++)
                        w0[q] = *(const float2*)(pw + (size_t)(base+16+q)*4096);
                }
                #pragma unroll
                for (int q=0;q<8;q++){
                    const int kk = base + 8 + q;
                    ulonglong2 n0 = *(const ulonglong2*)&shs[kk+1][0];
                    ulonglong2 n1 = *(const ulonglong2*)&shs[kk+1][4];
                    ull wd0=fdup(w1[q].x), wd1=fdup(w1[q].y);
                    FFMA2(acc[0][0],u0.x,wd0); FFMA2(acc[0][1],u0.y,wd0);
                    FFMA2(acc[0][2],u1.x,wd0); FFMA2(acc[0][3],u1.y,wd0);
                    FFMA2(acc[1][0],u0.x,wd1); FFMA2(acc[1][1],u0.y,wd1);
                    FFMA2(acc[1][2],u1.x,wd1); FFMA2(acc[1][3],u1.y,wd1);
                    u0 = n0; u1 = n1;
                }
            }

            // epilogue: columns j0,j0+1 -> (n = t>>3, m = 2g, 2g+1), g = t&7
            const int n  = t >> 3;
            const int g  = t & 7;
            float bias0 = b2sg[j0], bias1 = b2sg[j0+1];
            float cont[ROWS];
            #pragma unroll
            for (int p=0;p<4;p++){
                float a0, b0, a1, b1v;
                funpack(acc[0][p], a0, b0);
                funpack(acc[1][p], a1, b1v);
                cont[2*p]   = (a0  + bias0) * sz[2*p  ][2*g]
                            + (a1  + bias1) * sz[2*p  ][2*g+1];
                cont[2*p+1] = (b0  + bias0) * sz[2*p+1][2*g]
                            + (b1v + bias1) * sz[2*p+1][2*g+1];
            }
            #pragma unroll
            for (int b=0;b<ROWS;b++) sdp[g][n][b] = cont[b];
        }
        __syncthreads();

        // ---- y update + trajectory write (512 threads = 8 rows x 64 cols) ----
        {
            int n = t & 63, b = t >> 6;
            float yn = sy[b][n] + 0.01f * sdr[b][n];
            #pragma unroll
            for (int g=0; g<8; g++) yn += sdp[g][n][b];
            sy[b][n] = yn;
            out[((size_t)(k+1)*B_ + r0 + b)*N_ + n] = yn;
        }
        __syncthreads();
    }
}

extern "C" void kernel_launch(void* const* d_in, const int* in_sizes, int n_in,
                              void* d_out, int out_size)
{
    (void)in_sizes; (void)n_in; (void)out_size;
    nsde_kernel<<<B_/ROWS, NTHR>>>(
        (const float*)d_in[0],  // y0
        (const float*)d_in[1],  // controls
        (const float*)d_in[2],  // noise
        (const float*)d_in[3],  // W1_mu
        (const float*)d_in[4],  // b1_mu
        (const float*)d_in[5],  // W2_mu
        (const float*)d_in[6],  // b2_mu
        (const float*)d_in[7],  // W1_sg
        (const float*)d_in[8],  // b1_sg
        (const float*)d_in[9],  // W2_sg
        (const float*)d_in[10], // b2_sg
        (float*)d_out);
}